// round 1
// baseline (speedup 1.0000x reference)
#include <cuda_runtime.h>

#define NNODES 100000
#define NEDGES 1600000
#define FIN  128
#define FHID 128
#define FOUT 64

// Scratch (allocation-free rule: __device__ globals)
__device__ float g_dinv[NNODES];
__device__ float g_H  [NNODES * FHID];   // GEMM output (pre-aggregation messages)
__device__ float g_ACC[NNODES * FHID];   // aggregation accumulator / next-layer input

// ---------------- degree / norm ----------------

__global__ void deg_init(float* deg, int n) {
    int i = blockIdx.x * blockDim.x + threadIdx.x;
    if (i < n) deg[i] = 1.0f;               // self-loop
}

__global__ void deg_count(const int* __restrict__ dst, float* deg, int e) {
    int i = blockIdx.x * blockDim.x + threadIdx.x;
    if (i < e) atomicAdd(&deg[dst[i]], 1.0f);
}

__global__ void dinv_fin(float* deg, int n) {
    int i = blockIdx.x * blockDim.x + threadIdx.x;
    if (i < n) deg[i] = rsqrtf(deg[i]);
}

// ---------------- GEMM: H[n,NC] = (relu?)A[n,128] @ W[128,NC] ----------------
// block = 256 threads, tile 64 rows x NC cols, K chunked by 32.
// micro-tile per thread: 4 rows x (NC/16) cols, column block tx*TN (float4 LDS).

template<int NC, bool RELU>
__global__ __launch_bounds__(256) void gemm_k(const float* __restrict__ A,
                                              const float* __restrict__ W,
                                              float* __restrict__ H, int n) {
    constexpr int TN = NC / 16;
    __shared__ float sA[64][33];
    __shared__ float sW[32][NC];

    int tid = threadIdx.x;
    int tx = tid & 15, ty = tid >> 4;
    int row0 = blockIdx.x * 64;

    float acc[4][TN];
#pragma unroll
    for (int i = 0; i < 4; i++)
#pragma unroll
        for (int j = 0; j < TN; j++) acc[i][j] = 0.0f;

    for (int k0 = 0; k0 < 128; k0 += 32) {
        // load A chunk 64x32 (coalesced: consecutive tid -> consecutive kk)
#pragma unroll
        for (int i = 0; i < 8; i++) {
            int l = tid + i * 256;
            int r = l >> 5, kk = l & 31;
            int gr = row0 + r;
            float v = 0.0f;
            if (gr < n) v = __ldg(&A[gr * 128 + k0 + kk]);
            if (RELU) v = fmaxf(v, 0.0f);
            sA[r][kk] = v;
        }
        // load W chunk 32xNC
#pragma unroll
        for (int i = 0; i < (32 * NC) / 256; i++) {
            int l = tid + i * 256;
            int kk = l / NC, c = l % NC;
            sW[kk][c] = __ldg(&W[(k0 + kk) * NC + c]);
        }
        __syncthreads();

#pragma unroll
        for (int kk = 0; kk < 32; kk++) {
            float a0 = sA[ty * 4 + 0][kk];
            float a1 = sA[ty * 4 + 1][kk];
            float a2 = sA[ty * 4 + 2][kk];
            float a3 = sA[ty * 4 + 3][kk];
            // vector loads from sW: conflict-free (8 lanes x 16B = 128B phase)
#pragma unroll
            for (int jv = 0; jv < TN / 4; jv++) {
                float4 w4 = *reinterpret_cast<const float4*>(&sW[kk][tx * TN + jv * 4]);
                acc[0][jv * 4 + 0] = fmaf(a0, w4.x, acc[0][jv * 4 + 0]);
                acc[0][jv * 4 + 1] = fmaf(a0, w4.y, acc[0][jv * 4 + 1]);
                acc[0][jv * 4 + 2] = fmaf(a0, w4.z, acc[0][jv * 4 + 2]);
                acc[0][jv * 4 + 3] = fmaf(a0, w4.w, acc[0][jv * 4 + 3]);
                acc[1][jv * 4 + 0] = fmaf(a1, w4.x, acc[1][jv * 4 + 0]);
                acc[1][jv * 4 + 1] = fmaf(a1, w4.y, acc[1][jv * 4 + 1]);
                acc[1][jv * 4 + 2] = fmaf(a1, w4.z, acc[1][jv * 4 + 2]);
                acc[1][jv * 4 + 3] = fmaf(a1, w4.w, acc[1][jv * 4 + 3]);
                acc[2][jv * 4 + 0] = fmaf(a2, w4.x, acc[2][jv * 4 + 0]);
                acc[2][jv * 4 + 1] = fmaf(a2, w4.y, acc[2][jv * 4 + 1]);
                acc[2][jv * 4 + 2] = fmaf(a2, w4.z, acc[2][jv * 4 + 2]);
                acc[2][jv * 4 + 3] = fmaf(a2, w4.w, acc[2][jv * 4 + 3]);
                acc[3][jv * 4 + 0] = fmaf(a3, w4.x, acc[3][jv * 4 + 0]);
                acc[3][jv * 4 + 1] = fmaf(a3, w4.y, acc[3][jv * 4 + 1]);
                acc[3][jv * 4 + 2] = fmaf(a3, w4.z, acc[3][jv * 4 + 2]);
                acc[3][jv * 4 + 3] = fmaf(a3, w4.w, acc[3][jv * 4 + 3]);
            }
        }
        __syncthreads();
    }

    // store (float4)
#pragma unroll
    for (int i = 0; i < 4; i++) {
        int gr = row0 + ty * 4 + i;
        if (gr < n) {
            float4* o = reinterpret_cast<float4*>(H + gr * NC + tx * TN);
#pragma unroll
            for (int jv = 0; jv < TN / 4; jv++)
                o[jv] = make_float4(acc[i][jv * 4 + 0], acc[i][jv * 4 + 1],
                                    acc[i][jv * 4 + 2], acc[i][jv * 4 + 3]);
        }
    }
}

// ---------------- accumulator init: ACC = dinv^2 * H + b (self-loop + bias) ----------------

template<int F>
__global__ __launch_bounds__(256) void init_acc(const float* __restrict__ H,
                                                const float* __restrict__ dinv,
                                                const float* __restrict__ b,
                                                float* __restrict__ ACC, int n) {
    int idx = blockIdx.x * blockDim.x + threadIdx.x;  // float4 index
    int total = n * (F / 4);
    if (idx >= total) return;
    int v  = idx / (F / 4);
    int f4 = idx % (F / 4);
    float di = dinv[v];
    float s = di * di;
    float4 h  = reinterpret_cast<const float4*>(H)[idx];
    float4 bb = reinterpret_cast<const float4*>(b)[f4];
    float4 r;
    r.x = fmaf(h.x, s, bb.x);
    r.y = fmaf(h.y, s, bb.y);
    r.z = fmaf(h.z, s, bb.z);
    r.w = fmaf(h.w, s, bb.w);
    reinterpret_cast<float4*>(ACC)[idx] = r;
}

// ---------------- edge scatter: ACC[dst] += dinv[src]*dinv[dst] * H[src] ----------------
// one warp per edge; F=128 -> float4/lane, F=64 -> float2/lane

template<int F>
__global__ __launch_bounds__(256) void scatter_k(const float* __restrict__ H,
                                                 const int* __restrict__ src,
                                                 const int* __restrict__ dst,
                                                 const float* __restrict__ dinv,
                                                 float* __restrict__ ACC, int e) {
    int gw = (blockIdx.x * blockDim.x + threadIdx.x) >> 5;
    int lane = threadIdx.x & 31;
    if (gw >= e) return;
    int s = __ldg(&src[gw]);
    int d = __ldg(&dst[gw]);
    float nrm = __ldg(&dinv[s]) * __ldg(&dinv[d]);
    if (F == 128) {
        float4 v = reinterpret_cast<const float4*>(H + (long)s * F)[lane];
        float* out = ACC + (long)d * F + lane * 4;
        atomicAdd(out + 0, v.x * nrm);
        atomicAdd(out + 1, v.y * nrm);
        atomicAdd(out + 2, v.z * nrm);
        atomicAdd(out + 3, v.w * nrm);
    } else {
        float2 v = reinterpret_cast<const float2*>(H + (long)s * F)[lane];
        float* out = ACC + (long)d * F + lane * 2;
        atomicAdd(out + 0, v.x * nrm);
        atomicAdd(out + 1, v.y * nrm);
    }
}

// ---------------- launch ----------------

extern "C" void kernel_launch(void* const* d_in, const int* in_sizes, int n_in,
                              void* d_out, int out_size) {
    const float* x  = (const float*)d_in[0];
    const int*   ei = (const int*)  d_in[1];
    const float* W1 = (const float*)d_in[2];
    const float* b1 = (const float*)d_in[3];
    const float* W2 = (const float*)d_in[4];
    const float* b2 = (const float*)d_in[5];
    const float* W3 = (const float*)d_in[6];
    const float* b3 = (const float*)d_in[7];
    float* out = (float*)d_out;

    int n = in_sizes[0] / FIN;
    int e = in_sizes[1] / 2;
    const int* srcp = ei;
    const int* dstp = ei + e;

    float *dinv, *H, *ACC;
    cudaGetSymbolAddress((void**)&dinv, g_dinv);
    cudaGetSymbolAddress((void**)&H,    g_H);
    cudaGetSymbolAddress((void**)&ACC,  g_ACC);

    const int T = 256;
    int gN   = (n + T - 1) / T;
    int gE   = (e + T - 1) / T;
    int gM   = (n + 63) / 64;
    int gI128 = (n * (FHID / 4) + T - 1) / T;
    int gI64  = (n * (FOUT / 4) + T - 1) / T;
    int gS   = ((long)e * 32 + T - 1) / T;

    // degree norm
    deg_init<<<gN, T>>>(dinv, n);
    deg_count<<<gE, T>>>(dstp, dinv, e);
    dinv_fin<<<gN, T>>>(dinv, n);

    // layer 1: h = x@W1 ; acc = dinv^2*h + b1 ; scatter
    gemm_k<FHID, false><<<gM, T>>>(x, W1, H, n);
    init_acc<FHID><<<gI128, T>>>(H, dinv, b1, ACC, n);
    scatter_k<FHID><<<gS, T>>>(H, srcp, dstp, dinv, ACC, e);

    // layer 2: h = relu(acc)@W2 ; acc = dinv^2*h + b2 ; scatter
    gemm_k<FHID, true><<<gM, T>>>(ACC, W2, H, n);
    init_acc<FHID><<<gI128, T>>>(H, dinv, b2, ACC, n);
    scatter_k<FHID><<<gS, T>>>(H, srcp, dstp, dinv, ACC, e);

    // layer 3: h = relu(acc)@W3 ; out = dinv^2*h + b3 ; scatter (no relu after)
    gemm_k<FOUT, true><<<gM, T>>>(ACC, W3, H, n);
    init_acc<FOUT><<<gI64, T>>>(H, dinv, b3, out, n);
    scatter_k<FOUT><<<gS, T>>>(H, srcp, dstp, dinv, out, e);
}

// round 2
// speedup vs baseline: 2.7503x; 2.7503x over previous
#include <cuda_runtime.h>

#define NNODES 100000
#define NEDGES 1600000
#define FIN  128
#define FHID 128
#define FOUT 64

// Scratch (allocation-free rule: __device__ globals)
__device__ float g_dinv[NNODES];
__device__ int   g_deg [NNODES];
__device__ int   g_rowptr[NNODES];
__device__ int   g_cursor[NNODES];
__device__ int   g_adj [NEDGES];
__device__ int   g_blockSums[256];
__device__ float g_G  [NNODES * FHID];   // pre-scaled GEMM output (dinv[v]*h_v)
__device__ float g_ACC[NNODES * FHID];   // aggregated output / next-layer input

// ---------------- degree / norm / CSR build ----------------

__global__ void deg_zero(int* deg, int n) {
    int i = blockIdx.x * blockDim.x + threadIdx.x;
    if (i < n) deg[i] = 0;
}

__global__ void deg_count(const int* __restrict__ dst, int* deg, int e) {
    int i = blockIdx.x * blockDim.x + threadIdx.x;
    if (i < e) atomicAdd(&deg[dst[i]], 1);
}

__global__ void dinv_fin(const int* __restrict__ deg, float* dinv, int n) {
    int i = blockIdx.x * blockDim.x + threadIdx.x;
    if (i < n) dinv[i] = rsqrtf((float)(deg[i] + 1));   // +1 self-loop
}

// scan kernel 1: per-block sums of deg (512 per block)
__global__ __launch_bounds__(512) void scan1(const int* __restrict__ deg, int* blockSums, int n) {
    __shared__ int sm[512];
    int t = threadIdx.x;
    int i = blockIdx.x * 512 + t;
    sm[t] = (i < n) ? deg[i] : 0;
    __syncthreads();
    for (int o = 256; o > 0; o >>= 1) {
        if (t < o) sm[t] += sm[t + o];
        __syncthreads();
    }
    if (t == 0) blockSums[blockIdx.x] = sm[0];
}

// scan kernel 2: exclusive scan of blockSums (nb <= 256), single block
__global__ __launch_bounds__(256) void scan2(int* blockSums, int nb) {
    __shared__ int sm[256];
    int t = threadIdx.x;
    int v = (t < nb) ? blockSums[t] : 0;
    sm[t] = v;
    __syncthreads();
    for (int o = 1; o < 256; o <<= 1) {
        int x = (t >= o) ? sm[t - o] : 0;
        __syncthreads();
        sm[t] += x;
        __syncthreads();
    }
    if (t < nb) blockSums[t] = sm[t] - v;   // exclusive
}

// scan kernel 3: per-block exclusive scan + offset -> rowptr & cursor
__global__ __launch_bounds__(512) void scan3(const int* __restrict__ deg,
                                             const int* __restrict__ blockSums,
                                             int* rowptr, int* cursor, int n) {
    __shared__ int sm[512];
    int t = threadIdx.x;
    int i = blockIdx.x * 512 + t;
    int v = (i < n) ? deg[i] : 0;
    sm[t] = v;
    __syncthreads();
    for (int o = 1; o < 512; o <<= 1) {
        int x = (t >= o) ? sm[t - o] : 0;
        __syncthreads();
        sm[t] += x;
        __syncthreads();
    }
    if (i < n) {
        int r = blockSums[blockIdx.x] + sm[t] - v;   // exclusive
        rowptr[i] = r;
        cursor[i] = r;
    }
}

__global__ void fill_adj(const int* __restrict__ src, const int* __restrict__ dst,
                         int* cursor, int* adj, int e) {
    int i = blockIdx.x * blockDim.x + threadIdx.x;
    if (i < e) {
        int pos = atomicAdd(&cursor[dst[i]], 1);
        adj[pos] = src[i];
    }
}

// ---------------- GEMM: G[n,NC] = dinv[row] * ((relu?)A[n,128] @ W[128,NC]) ----------------

template<int NC, bool RELU>
__global__ __launch_bounds__(256) void gemm_k(const float* __restrict__ A,
                                              const float* __restrict__ W,
                                              const float* __restrict__ dinv,
                                              float* __restrict__ G, int n) {
    constexpr int TN = NC / 16;
    __shared__ float sA[64][33];
    __shared__ float sW[32][NC];

    int tid = threadIdx.x;
    int tx = tid & 15, ty = tid >> 4;
    int row0 = blockIdx.x * 64;

    float acc[4][TN];
#pragma unroll
    for (int i = 0; i < 4; i++)
#pragma unroll
        for (int j = 0; j < TN; j++) acc[i][j] = 0.0f;

    for (int k0 = 0; k0 < 128; k0 += 32) {
#pragma unroll
        for (int i = 0; i < 8; i++) {
            int l = tid + i * 256;
            int r = l >> 5, kk = l & 31;
            int gr = row0 + r;
            float v = 0.0f;
            if (gr < n) v = __ldg(&A[gr * 128 + k0 + kk]);
            if (RELU) v = fmaxf(v, 0.0f);
            sA[r][kk] = v;
        }
#pragma unroll
        for (int i = 0; i < (32 * NC) / 256; i++) {
            int l = tid + i * 256;
            int kk = l / NC, c = l % NC;
            sW[kk][c] = __ldg(&W[(k0 + kk) * NC + c]);
        }
        __syncthreads();

#pragma unroll
        for (int kk = 0; kk < 32; kk++) {
            float a0 = sA[ty * 4 + 0][kk];
            float a1 = sA[ty * 4 + 1][kk];
            float a2 = sA[ty * 4 + 2][kk];
            float a3 = sA[ty * 4 + 3][kk];
#pragma unroll
            for (int jv = 0; jv < TN / 4; jv++) {
                float4 w4 = *reinterpret_cast<const float4*>(&sW[kk][tx * TN + jv * 4]);
                acc[0][jv * 4 + 0] = fmaf(a0, w4.x, acc[0][jv * 4 + 0]);
                acc[0][jv * 4 + 1] = fmaf(a0, w4.y, acc[0][jv * 4 + 1]);
                acc[0][jv * 4 + 2] = fmaf(a0, w4.z, acc[0][jv * 4 + 2]);
                acc[0][jv * 4 + 3] = fmaf(a0, w4.w, acc[0][jv * 4 + 3]);
                acc[1][jv * 4 + 0] = fmaf(a1, w4.x, acc[1][jv * 4 + 0]);
                acc[1][jv * 4 + 1] = fmaf(a1, w4.y, acc[1][jv * 4 + 1]);
                acc[1][jv * 4 + 2] = fmaf(a1, w4.z, acc[1][jv * 4 + 2]);
                acc[1][jv * 4 + 3] = fmaf(a1, w4.w, acc[1][jv * 4 + 3]);
                acc[2][jv * 4 + 0] = fmaf(a2, w4.x, acc[2][jv * 4 + 0]);
                acc[2][jv * 4 + 1] = fmaf(a2, w4.y, acc[2][jv * 4 + 1]);
                acc[2][jv * 4 + 2] = fmaf(a2, w4.z, acc[2][jv * 4 + 2]);
                acc[2][jv * 4 + 3] = fmaf(a2, w4.w, acc[2][jv * 4 + 3]);
                acc[3][jv * 4 + 0] = fmaf(a3, w4.x, acc[3][jv * 4 + 0]);
                acc[3][jv * 4 + 1] = fmaf(a3, w4.y, acc[3][jv * 4 + 1]);
                acc[3][jv * 4 + 2] = fmaf(a3, w4.z, acc[3][jv * 4 + 2]);
                acc[3][jv * 4 + 3] = fmaf(a3, w4.w, acc[3][jv * 4 + 3]);
            }
        }
        __syncthreads();
    }

#pragma unroll
    for (int i = 0; i < 4; i++) {
        int gr = row0 + ty * 4 + i;
        if (gr < n) {
            float sc = __ldg(&dinv[gr]);
            float4* o = reinterpret_cast<float4*>(G + gr * NC + tx * TN);
#pragma unroll
            for (int jv = 0; jv < TN / 4; jv++)
                o[jv] = make_float4(acc[i][jv * 4 + 0] * sc, acc[i][jv * 4 + 1] * sc,
                                    acc[i][jv * 4 + 2] * sc, acc[i][jv * 4 + 3] * sc);
        }
    }
}

// ---------------- gather aggregate: OUT[d] = dinv[d]*(G[d] + sum_{src in N(d)} G[src]) + b ----------------
// one warp per dst node

template<int F>
__global__ __launch_bounds__(256) void gather_k(const float* __restrict__ G,
                                                const int* __restrict__ adj,
                                                const int* __restrict__ rowptr,
                                                const int* __restrict__ deg,
                                                const float* __restrict__ dinv,
                                                const float* __restrict__ b,
                                                float* __restrict__ OUT, int n) {
    int gw = (blockIdx.x * blockDim.x + threadIdx.x) >> 5;
    int lane = threadIdx.x & 31;
    if (gw >= n) return;

    int start = rowptr[gw];
    int cnt = deg[gw];

    if (F == 128) {
        // self term
        float4 acc = reinterpret_cast<const float4*>(G + (long)gw * F)[lane];
        for (int c = 0; c < cnt; c += 32) {
            int my = -1;
            if (c + lane < cnt) my = __ldg(&adj[start + c + lane]);
            int mend = min(32, cnt - c);
            for (int m = 0; m < mend; m++) {
                int s = __shfl_sync(0xffffffffu, my, m);
                float4 v = reinterpret_cast<const float4*>(G + (long)s * F)[lane];
                acc.x += v.x; acc.y += v.y; acc.z += v.z; acc.w += v.w;
            }
        }
        float sc = dinv[gw];
        float4 bb = reinterpret_cast<const float4*>(b)[lane];
        float4 r;
        r.x = fmaf(acc.x, sc, bb.x);
        r.y = fmaf(acc.y, sc, bb.y);
        r.z = fmaf(acc.z, sc, bb.z);
        r.w = fmaf(acc.w, sc, bb.w);
        reinterpret_cast<float4*>(OUT + (long)gw * F)[lane] = r;
    } else {
        float2 acc = reinterpret_cast<const float2*>(G + (long)gw * F)[lane];
        for (int c = 0; c < cnt; c += 32) {
            int my = -1;
            if (c + lane < cnt) my = __ldg(&adj[start + c + lane]);
            int mend = min(32, cnt - c);
            for (int m = 0; m < mend; m++) {
                int s = __shfl_sync(0xffffffffu, my, m);
                float2 v = reinterpret_cast<const float2*>(G + (long)s * F)[lane];
                acc.x += v.x; acc.y += v.y;
            }
        }
        float sc = dinv[gw];
        float2 bb = reinterpret_cast<const float2*>(b)[lane];
        float2 r;
        r.x = fmaf(acc.x, sc, bb.x);
        r.y = fmaf(acc.y, sc, bb.y);
        reinterpret_cast<float2*>(OUT + (long)gw * F)[lane] = r;
    }
}

// ---------------- launch ----------------

extern "C" void kernel_launch(void* const* d_in, const int* in_sizes, int n_in,
                              void* d_out, int out_size) {
    const float* x  = (const float*)d_in[0];
    const int*   ei = (const int*)  d_in[1];
    const float* W1 = (const float*)d_in[2];
    const float* b1 = (const float*)d_in[3];
    const float* W2 = (const float*)d_in[4];
    const float* b2 = (const float*)d_in[5];
    const float* W3 = (const float*)d_in[6];
    const float* b3 = (const float*)d_in[7];
    float* out = (float*)d_out;

    int n = in_sizes[0] / FIN;
    int e = in_sizes[1] / 2;
    const int* srcp = ei;
    const int* dstp = ei + e;

    float *dinv, *G, *ACC;
    int *deg, *rowptr, *cursor, *adj, *blockSums;
    cudaGetSymbolAddress((void**)&dinv, g_dinv);
    cudaGetSymbolAddress((void**)&deg,  g_deg);
    cudaGetSymbolAddress((void**)&rowptr, g_rowptr);
    cudaGetSymbolAddress((void**)&cursor, g_cursor);
    cudaGetSymbolAddress((void**)&adj,  g_adj);
    cudaGetSymbolAddress((void**)&blockSums, g_blockSums);
    cudaGetSymbolAddress((void**)&G,    g_G);
    cudaGetSymbolAddress((void**)&ACC,  g_ACC);

    const int T = 256;
    int gN = (n + T - 1) / T;
    int gE = (e + T - 1) / T;
    int gM = (n + 63) / 64;
    int nb = (n + 511) / 512;            // scan blocks (196 for N=100000)
    int gW = (n * 32 + T - 1) / T;       // warp-per-node grids

    // ---- CSR build ----
    deg_zero<<<gN, T>>>(deg, n);
    deg_count<<<gE, T>>>(dstp, deg, e);
    dinv_fin<<<gN, T>>>(deg, dinv, n);
    scan1<<<nb, 512>>>(deg, blockSums, n);
    scan2<<<1, 256>>>(blockSums, nb);
    scan3<<<nb, 512>>>(deg, blockSums, rowptr, cursor, n);
    fill_adj<<<gE, T>>>(srcp, dstp, cursor, adj, e);

    // ---- layer 1 ----
    gemm_k<FHID, false><<<gM, T>>>(x, W1, dinv, G, n);
    gather_k<FHID><<<gW, T>>>(G, adj, rowptr, deg, dinv, b1, ACC, n);

    // ---- layer 2 ----
    gemm_k<FHID, true><<<gM, T>>>(ACC, W2, dinv, G, n);
    gather_k<FHID><<<gW, T>>>(G, adj, rowptr, deg, dinv, b2, ACC, n);

    // ---- layer 3 ----
    gemm_k<FOUT, true><<<gM, T>>>(ACC, W3, dinv, G, n);
    gather_k<FOUT><<<gW, T>>>(G, adj, rowptr, deg, dinv, b3, out, n);
}

// round 3
// speedup vs baseline: 3.1179x; 1.1337x over previous
#include <cuda_runtime.h>

#define NNODES 100000
#define NEDGES 1600000
#define FIN  128
#define FHID 128
#define FOUT 64

// Scratch (allocation-free rule: __device__ globals)
__device__ float g_dinv[NNODES];
__device__ int   g_deg [NNODES];
__device__ int   g_rowptr[NNODES];
__device__ int   g_cursor[NNODES];
__device__ int   g_adj [NEDGES];
__device__ int   g_blockSums[256];
__device__ float g_G  [NNODES * FHID];   // pre-scaled GEMM output (dinv[v]*h_v)
__device__ float g_ACC[NNODES * FHID];   // aggregated output / next-layer input

// ---------------- degree / norm / CSR build ----------------

__global__ void deg_zero(int* deg, int n) {
    int i = blockIdx.x * blockDim.x + threadIdx.x;
    if (i < n) deg[i] = 0;
}

__global__ void deg_count(const int* __restrict__ dst, int* deg, int e) {
    int i = blockIdx.x * blockDim.x + threadIdx.x;
    if (i < e) atomicAdd(&deg[dst[i]], 1);
}

__global__ void dinv_fin(const int* __restrict__ deg, float* dinv, int n) {
    int i = blockIdx.x * blockDim.x + threadIdx.x;
    if (i < n) dinv[i] = rsqrtf((float)(deg[i] + 1));   // +1 self-loop
}

__global__ __launch_bounds__(512) void scan1(const int* __restrict__ deg, int* blockSums, int n) {
    __shared__ int sm[512];
    int t = threadIdx.x;
    int i = blockIdx.x * 512 + t;
    sm[t] = (i < n) ? deg[i] : 0;
    __syncthreads();
    for (int o = 256; o > 0; o >>= 1) {
        if (t < o) sm[t] += sm[t + o];
        __syncthreads();
    }
    if (t == 0) blockSums[blockIdx.x] = sm[0];
}

__global__ __launch_bounds__(256) void scan2(int* blockSums, int nb) {
    __shared__ int sm[256];
    int t = threadIdx.x;
    int v = (t < nb) ? blockSums[t] : 0;
    sm[t] = v;
    __syncthreads();
    for (int o = 1; o < 256; o <<= 1) {
        int x = (t >= o) ? sm[t - o] : 0;
        __syncthreads();
        sm[t] += x;
        __syncthreads();
    }
    if (t < nb) blockSums[t] = sm[t] - v;   // exclusive
}

__global__ __launch_bounds__(512) void scan3(const int* __restrict__ deg,
                                             const int* __restrict__ blockSums,
                                             int* rowptr, int* cursor, int n) {
    __shared__ int sm[512];
    int t = threadIdx.x;
    int i = blockIdx.x * 512 + t;
    int v = (i < n) ? deg[i] : 0;
    sm[t] = v;
    __syncthreads();
    for (int o = 1; o < 512; o <<= 1) {
        int x = (t >= o) ? sm[t - o] : 0;
        __syncthreads();
        sm[t] += x;
        __syncthreads();
    }
    if (i < n) {
        int r = blockSums[blockIdx.x] + sm[t] - v;   // exclusive
        rowptr[i] = r;
        cursor[i] = r;
    }
}

__global__ void fill_adj(const int* __restrict__ src, const int* __restrict__ dst,
                         int* cursor, int* adj, int e) {
    int i = blockIdx.x * blockDim.x + threadIdx.x;
    if (i < e) {
        int pos = atomicAdd(&cursor[dst[i]], 1);
        adj[pos] = src[i];
    }
}

// ---------------- GEMM: G[n,NC] = dinv[row] * ((relu?)A[n,128] @ W[128,NC]) ----------------
// Tile: BM=128, BN=NC, BK=16. 256 threads (tx 0..15, ty 0..15).
// Micro-tile: 8 rows (ty*8) x 8 cols as NV float4 groups at {v*64 + tx*4}.
// sA padded stride 20 ([m][k]); sW [k][NC]; b-fetch conflict-free (tx*16B consecutive).

template<int NC, bool RELU>
__global__ __launch_bounds__(256, 2) void gemm_k(const float* __restrict__ A,
                                                 const float* __restrict__ W,
                                                 const float* __restrict__ dinv,
                                                 float* __restrict__ G, int n) {
    constexpr int NV = NC / 64;   // float4 col-groups per thread (2 for 128, 1 for 64)
    __shared__ float sA[128][20];
    __shared__ float sW[16][NC];

    int tid = threadIdx.x;
    int tx = tid & 15, ty = tid >> 4;
    int row0 = blockIdx.x * 128;

    float acc[8][4 * NV];
#pragma unroll
    for (int i = 0; i < 8; i++)
#pragma unroll
        for (int j = 0; j < 4 * NV; j++) acc[i][j] = 0.0f;

#pragma unroll 1
    for (int k0 = 0; k0 < 128; k0 += 16) {
        // load A tile: 128 rows x 16 k, float4 per thread x2
#pragma unroll
        for (int p = 0; p < 2; p++) {
            int r = p * 64 + (tid >> 2);
            int kk4 = (tid & 3) * 4;
            int gr = row0 + r;
            float4 v = make_float4(0.f, 0.f, 0.f, 0.f);
            if (gr < n) v = *reinterpret_cast<const float4*>(&A[gr * 128 + k0 + kk4]);
            if (RELU) {
                v.x = fmaxf(v.x, 0.f); v.y = fmaxf(v.y, 0.f);
                v.z = fmaxf(v.z, 0.f); v.w = fmaxf(v.w, 0.f);
            }
            sA[r][kk4 + 0] = v.x; sA[r][kk4 + 1] = v.y;
            sA[r][kk4 + 2] = v.z; sA[r][kk4 + 3] = v.w;
        }
        // load W tile: 16 x NC, float4-coalesced
#pragma unroll
        for (int q = 0; q < NC / 64; q++) {
            int l = tid + q * 256;
            int kk = l / (NC / 4), c4 = l % (NC / 4);
            *reinterpret_cast<float4*>(&sW[kk][c4 * 4]) =
                *reinterpret_cast<const float4*>(&W[(k0 + kk) * NC + c4 * 4]);
        }
        __syncthreads();

#pragma unroll
        for (int kk = 0; kk < 16; kk++) {
            float a[8];
#pragma unroll
            for (int i = 0; i < 8; i++) a[i] = sA[ty * 8 + i][kk];
#pragma unroll
            for (int v = 0; v < NV; v++) {
                float4 b = *reinterpret_cast<const float4*>(&sW[kk][v * 64 + tx * 4]);
#pragma unroll
                for (int i = 0; i < 8; i++) {
                    acc[i][v * 4 + 0] = fmaf(a[i], b.x, acc[i][v * 4 + 0]);
                    acc[i][v * 4 + 1] = fmaf(a[i], b.y, acc[i][v * 4 + 1]);
                    acc[i][v * 4 + 2] = fmaf(a[i], b.z, acc[i][v * 4 + 2]);
                    acc[i][v * 4 + 3] = fmaf(a[i], b.w, acc[i][v * 4 + 3]);
                }
            }
        }
        __syncthreads();
    }

#pragma unroll
    for (int i = 0; i < 8; i++) {
        int gr = row0 + ty * 8 + i;
        if (gr < n) {
            float sc = __ldg(&dinv[gr]);
#pragma unroll
            for (int v = 0; v < NV; v++) {
                float4 r = make_float4(acc[i][v * 4 + 0] * sc, acc[i][v * 4 + 1] * sc,
                                       acc[i][v * 4 + 2] * sc, acc[i][v * 4 + 3] * sc);
                *reinterpret_cast<float4*>(&G[gr * NC + v * 64 + tx * 4]) = r;
            }
        }
    }
}

// ---------------- gather aggregate: OUT[d] = dinv[d]*(G[d] + sum_{src in N(d)} G[src]) + b ----------------
// one warp per dst node; neighbor loop unrolled x4 for MLP

template<int F>
__global__ __launch_bounds__(256) void gather_k(const float* __restrict__ G,
                                                const int* __restrict__ adj,
                                                const int* __restrict__ rowptr,
                                                const int* __restrict__ deg,
                                                const float* __restrict__ dinv,
                                                const float* __restrict__ b,
                                                float* __restrict__ OUT, int n) {
    int gw = (blockIdx.x * blockDim.x + threadIdx.x) >> 5;
    int lane = threadIdx.x & 31;
    if (gw >= n) return;

    int start = rowptr[gw];
    int cnt = deg[gw];

    if (F == 128) {
        float4 acc = reinterpret_cast<const float4*>(G + (long)gw * F)[lane];
        for (int c = 0; c < cnt; c += 32) {
            int my = 0;
            if (c + lane < cnt) my = __ldg(&adj[start + c + lane]);
            int mend = min(32, cnt - c);
            int m = 0;
            for (; m + 4 <= mend; m += 4) {
                int s0 = __shfl_sync(0xffffffffu, my, m + 0);
                int s1 = __shfl_sync(0xffffffffu, my, m + 1);
                int s2 = __shfl_sync(0xffffffffu, my, m + 2);
                int s3 = __shfl_sync(0xffffffffu, my, m + 3);
                float4 v0 = reinterpret_cast<const float4*>(G + (long)s0 * F)[lane];
                float4 v1 = reinterpret_cast<const float4*>(G + (long)s1 * F)[lane];
                float4 v2 = reinterpret_cast<const float4*>(G + (long)s2 * F)[lane];
                float4 v3 = reinterpret_cast<const float4*>(G + (long)s3 * F)[lane];
                acc.x += v0.x + v1.x + v2.x + v3.x;
                acc.y += v0.y + v1.y + v2.y + v3.y;
                acc.z += v0.z + v1.z + v2.z + v3.z;
                acc.w += v0.w + v1.w + v2.w + v3.w;
            }
            for (; m < mend; m++) {
                int s = __shfl_sync(0xffffffffu, my, m);
                float4 v = reinterpret_cast<const float4*>(G + (long)s * F)[lane];
                acc.x += v.x; acc.y += v.y; acc.z += v.z; acc.w += v.w;
            }
        }
        float sc = dinv[gw];
        float4 bb = reinterpret_cast<const float4*>(b)[lane];
        float4 r;
        r.x = fmaf(acc.x, sc, bb.x);
        r.y = fmaf(acc.y, sc, bb.y);
        r.z = fmaf(acc.z, sc, bb.z);
        r.w = fmaf(acc.w, sc, bb.w);
        reinterpret_cast<float4*>(OUT + (long)gw * F)[lane] = r;
    } else {
        float2 acc = reinterpret_cast<const float2*>(G + (long)gw * F)[lane];
        for (int c = 0; c < cnt; c += 32) {
            int my = 0;
            if (c + lane < cnt) my = __ldg(&adj[start + c + lane]);
            int mend = min(32, cnt - c);
            int m = 0;
            for (; m + 4 <= mend; m += 4) {
                int s0 = __shfl_sync(0xffffffffu, my, m + 0);
                int s1 = __shfl_sync(0xffffffffu, my, m + 1);
                int s2 = __shfl_sync(0xffffffffu, my, m + 2);
                int s3 = __shfl_sync(0xffffffffu, my, m + 3);
                float2 v0 = reinterpret_cast<const float2*>(G + (long)s0 * F)[lane];
                float2 v1 = reinterpret_cast<const float2*>(G + (long)s1 * F)[lane];
                float2 v2 = reinterpret_cast<const float2*>(G + (long)s2 * F)[lane];
                float2 v3 = reinterpret_cast<const float2*>(G + (long)s3 * F)[lane];
                acc.x += v0.x + v1.x + v2.x + v3.x;
                acc.y += v0.y + v1.y + v2.y + v3.y;
            }
            for (; m < mend; m++) {
                int s = __shfl_sync(0xffffffffu, my, m);
                float2 v = reinterpret_cast<const float2*>(G + (long)s * F)[lane];
                acc.x += v.x; acc.y += v.y;
            }
        }
        float sc = dinv[gw];
        float2 bb = reinterpret_cast<const float2*>(b)[lane];
        float2 r;
        r.x = fmaf(acc.x, sc, bb.x);
        r.y = fmaf(acc.y, sc, bb.y);
        reinterpret_cast<float2*>(OUT + (long)gw * F)[lane] = r;
    }
}

// ---------------- launch ----------------

extern "C" void kernel_launch(void* const* d_in, const int* in_sizes, int n_in,
                              void* d_out, int out_size) {
    const float* x  = (const float*)d_in[0];
    const int*   ei = (const int*)  d_in[1];
    const float* W1 = (const float*)d_in[2];
    const float* b1 = (const float*)d_in[3];
    const float* W2 = (const float*)d_in[4];
    const float* b2 = (const float*)d_in[5];
    const float* W3 = (const float*)d_in[6];
    const float* b3 = (const float*)d_in[7];
    float* out = (float*)d_out;

    int n = in_sizes[0] / FIN;
    int e = in_sizes[1] / 2;
    const int* srcp = ei;
    const int* dstp = ei + e;

    float *dinv, *G, *ACC;
    int *deg, *rowptr, *cursor, *adj, *blockSums;
    cudaGetSymbolAddress((void**)&dinv, g_dinv);
    cudaGetSymbolAddress((void**)&deg,  g_deg);
    cudaGetSymbolAddress((void**)&rowptr, g_rowptr);
    cudaGetSymbolAddress((void**)&cursor, g_cursor);
    cudaGetSymbolAddress((void**)&adj,  g_adj);
    cudaGetSymbolAddress((void**)&blockSums, g_blockSums);
    cudaGetSymbolAddress((void**)&G,    g_G);
    cudaGetSymbolAddress((void**)&ACC,  g_ACC);

    const int T = 256;
    int gN = (n + T - 1) / T;
    int gE = (e + T - 1) / T;
    int gM = (n + 127) / 128;            // 128-row GEMM tiles
    int nb = (n + 511) / 512;
    int gW = (n * 32 + T - 1) / T;       // warp-per-node grids

    // ---- CSR build ----
    deg_zero<<<gN, T>>>(deg, n);
    deg_count<<<gE, T>>>(dstp, deg, e);
    dinv_fin<<<gN, T>>>(deg, dinv, n);
    scan1<<<nb, 512>>>(deg, blockSums, n);
    scan2<<<1, 256>>>(blockSums, nb);
    scan3<<<nb, 512>>>(deg, blockSums, rowptr, cursor, n);
    fill_adj<<<gE, T>>>(srcp, dstp, cursor, adj, e);

    // ---- layer 1 ----
    gemm_k<FHID, false><<<gM, T>>>(x, W1, dinv, G, n);
    gather_k<FHID><<<gW, T>>>(G, adj, rowptr, deg, dinv, b1, ACC, n);

    // ---- layer 2 ----
    gemm_k<FHID, true><<<gM, T>>>(ACC, W2, dinv, G, n);
    gather_k<FHID><<<gW, T>>>(G, adj, rowptr, deg, dinv, b2, ACC, n);

    // ---- layer 3 ----
    gemm_k<FOUT, true><<<gM, T>>>(ACC, W3, dinv, G, n);
    gather_k<FOUT><<<gW, T>>>(G, adj, rowptr, deg, dinv, b3, out, n);
}